// round 11
// baseline (speedup 1.0000x reference)
#include <cuda_runtime.h>
#include <math.h>

#define FULL 0xFFFFFFFFu
using ull = unsigned long long;

constexpr int D  = 32;
constexpr int N  = 10;
constexpr int H  = 4;
constexpr int DP = 16;   // dim-pairs; 16 lanes/group, 2 groups/warp

constexpr ull SGN2 = 0x8000000080000000ULL;
constexpr ull ABS2 = 0x7FFFFFFF7FFFFFFFULL;

__device__ __forceinline__ ull pk2(float lo, float hi) {
    ull r; asm("mov.b64 %0,{%1,%2};" : "=l"(r) : "f"(lo), "f"(hi)); return r;
}
__device__ __forceinline__ ull dup2(float v) {
    ull r; asm("mov.b64 %0,{%1,%1};" : "=l"(r) : "f"(v)); return r;
}
__device__ __forceinline__ void up2(ull p, float& lo, float& hi) {
    asm("mov.b64 {%0,%1},%2;" : "=f"(lo), "=f"(hi) : "l"(p));
}
__device__ __forceinline__ ull fma2(ull a, ull b, ull c) {
    ull r; asm("fma.rn.f32x2 %0,%1,%2,%3;" : "=l"(r) : "l"(a), "l"(b), "l"(c)); return r;
}
__device__ __forceinline__ ull add2(ull a, ull b) {
    ull r; asm("add.rn.f32x2 %0,%1,%2;" : "=l"(r) : "l"(a), "l"(b)); return r;
}
__device__ __forceinline__ ull mul2(ull a, ull b) {
    ull r; asm("mul.rn.f32x2 %0,%1,%2;" : "=l"(r) : "l"(a), "l"(b)); return r;
}
__device__ __forceinline__ void cpa16(unsigned s, const void* g) {
    asm volatile("cp.async.cg.shared.global [%0],[%1],16;" :: "r"(s), "l"(g));
}
#define CPA_COMMIT() asm volatile("cp.async.commit_group;" ::: "memory")
#define CPA_WAIT1()  asm volatile("cp.async.wait_group 1;" ::: "memory")

struct WB {
    ulonglong2 kbuf[2][160];  // k staging, PRE-SWIZZLED; cur buf reused for xv-dup
    ulonglong2 pbuf[2][20];   // pos
    ulonglong2 qbuf[2][16];   // q
    float ph[80];             // relu'd pos-MLP hidden units (row*4+c)
    float yv[80];             // relu'd score-MLP hidden units (row*4+c)
    float uq[8];              // per-group c-constants: ab1+cb-q.Fq
};

__global__ void __launch_bounds__(128, 4) attn2d_kernel(
    const float* __restrict__ q,   const float* __restrict__ k,
    const float* __restrict__ pos, const int*   __restrict__ mask,
    const float* __restrict__ Wq,  const float* __restrict__ Wk,
    const float* __restrict__ Wv,
    const float* __restrict__ pW1, const float* __restrict__ pb1,
    const float* __restrict__ pW2, const float* __restrict__ pb2,
    const float* __restrict__ aW1, const float* __restrict__ ab1,
    const float* __restrict__ aW2, const float* __restrict__ ab2,
    const float* __restrict__ oW,  const float* __restrict__ ob,
    ull* __restrict__ out_x,  ull* __restrict__ out_attn,
    ull* __restrict__ out_std, ull* __restrict__ out_nstd,
    int G)
{
    // j-pair packed projection weights: sWkJ[j2][d] = (Wk[2j2][d], Wk[2j2+1][d])
    __shared__ __align__(16) ull sWkJ[16][32];
    __shared__ __align__(16) ull sWvJ[16][32];
    // h-pair packed epilogue weights
    __shared__ __align__(16) ull sP2J[2][32];   // (pW2[2h][d], pW2[2h+1][d])
    __shared__ __align__(16) ull sA2J[2][32];   // (aW2[2h][d], aW2[2h+1][d])
    __shared__ __align__(16) ulonglong2 sOWP[16][16];
    __shared__ __align__(16) ulonglong2 sFk[4][9];
    __shared__ __align__(16) ulonglong2 sFq[4][9];
    __shared__ __align__(16) float sM[4][4];
    __shared__ float sCB[4];
    __shared__ __align__(16) WB wbuf[4];

    const int tid = threadIdx.x;
    // ---- phase 0: fused weights + big-weight staging ----
    float* tmpF = (float*)wbuf[0].kbuf;   // 256 floats: Fk then Fq, idx j*4+c
    {
        const int j = tid >> 2, c = tid & 3;
        float fk = 0.f, fq = 0.f;
        for (int d = 0; d < D; d++) {
            const float a = aW1[d * H + c];
            fk = fmaf(Wk[j * D + d], a, fk);
            fq = fmaf(Wq[j * D + d], a, fq);
        }
        tmpF[tid] = fk; tmpF[128 + tid] = fq;
    }
    for (int i = tid; i < 512; i += 128) {   // j-pair packs
        const int j2 = i >> 5, d = i & 31;
        sWkJ[j2][d] = pk2(Wk[(2*j2)*D + d], Wk[(2*j2+1)*D + d]);
        sWvJ[j2][d] = pk2(Wv[(2*j2)*D + d], Wv[(2*j2+1)*D + d]);
    }
    if (tid < 64) {
        const int h2 = tid >> 5, d = tid & 31;
        sP2J[h2][d] = pk2(pW2[(2*h2)*D + d], pW2[(2*h2+1)*D + d]);
        sA2J[h2][d] = pk2(aW2[(2*h2)*D + d], aW2[(2*h2+1)*D + d]);
    }
    for (int i = tid; i < 256; i += 128) {   // oW row-pair interleave
        const int j2 = i >> 4, gl2 = (i & 15) * 2;
        ulonglong2 t;
        t.x = pk2(oW[(2*j2)*D + gl2],   oW[(2*j2)*D + gl2+1]);
        t.y = pk2(oW[(2*j2+1)*D + gl2], oW[(2*j2+1)*D + gl2+1]);
        sOWP[j2][i & 15] = t;
    }
    if (tid < 16) {
        const int h = tid >> 2, c = tid & 3;
        float m = 0.f;
        for (int d = 0; d < D; d++) m = fmaf(pW2[h * D + d], aW1[d * H + c], m);
        sM[c][h] = m;
    }
    if (tid < 4) {
        float cb = ab1[tid];
        for (int d = 0; d < D; d++) cb = fmaf(pb2[d], aW1[d * H + tid], cb);
        sCB[tid] = cb;
    }
    __syncthreads();
    if (tid < 32) {   // repack fused weights by column
        const int c = tid >> 3, jj = tid & 7;
        ulonglong2 t;
        t.x = pk2(tmpF[(4*jj+0)*4 + c], tmpF[(4*jj+1)*4 + c]);
        t.y = pk2(tmpF[(4*jj+2)*4 + c], tmpF[(4*jj+3)*4 + c]);
        sFk[c][jj] = t;
        t.x = pk2(tmpF[128 + (4*jj+0)*4 + c], tmpF[128 + (4*jj+1)*4 + c]);
        t.y = pk2(tmpF[128 + (4*jj+2)*4 + c], tmpF[128 + (4*jj+3)*4 + c]);
        sFq[c][jj] = t;
    }
    __syncthreads();

    const int lane = tid & 31, gl = lane & 15, hf = lane >> 4, w = tid >> 5;
    const int d2 = 2 * gl;
    const int cML = lane & 3;
    const float pb1c = pb1[cML];
    const float pw1c0 = pW1[0*H + cML], pw1c1 = pW1[1*H + cML];
    const float pw1c2 = pW1[2*H + cML], pw1c3 = pW1[3*H + cML];

    // hoisted per-lane h-pair epilogue weights (replaces a2p/p2p arrays)
    const ulonglong2 wpA = *(const ulonglong2*)&sP2J[0][d2];
    const ulonglong2 wpB = *(const ulonglong2*)&sP2J[1][d2];
    const ulonglong2 waA = *(const ulonglong2*)&sA2J[0][d2];
    const ulonglong2 waB = *(const ulonglong2*)&sA2J[1][d2];
    const ull pb2p = pk2(pb2[d2], pb2[d2 + 1]);
    const ull ab2p = pk2(ab2[d2], ab2[d2 + 1]);
    const ull obp  = pk2(ob[d2],  ob[d2 + 1]);

    WB& wb = wbuf[w];
    const int warpsTotal = (gridDim.x * blockDim.x) >> 5;
    const int warpG = (blockIdx.x * blockDim.x + tid) >> 5;
    const int GP = G >> 1;

    auto prefetch = [&](int pp, int nb) {
        const ulonglong2* kf = (const ulonglong2*)k + (size_t)pp * 160;
        ulonglong2* kb = wb.kbuf[nb];
#pragma unroll
        for (int i = 0; i < 5; i++) {
            const int flat = i * 32 + lane;
            const int row = flat >> 3, j4 = flat & 7;
            cpa16((unsigned)__cvta_generic_to_shared(kb + row * 8 + (j4 ^ (row & 7))),
                  kf + flat);
        }
        if (lane < 16)
            cpa16((unsigned)__cvta_generic_to_shared(&wb.qbuf[nb][lane]),
                  (const ulonglong2*)q + (size_t)pp * 16 + lane);
        if (lane < 20)
            cpa16((unsigned)__cvta_generic_to_shared(&wb.pbuf[nb][lane]),
                  (const ulonglong2*)pos + (size_t)pp * 20 + lane);
        CPA_COMMIT();
    };

    int mnext = 0;
    if (warpG < GP) {
        prefetch(warpG, 0);
        if (lane < 20) mnext = __ldg(mask + (size_t)warpG * 20 + lane);
    }

    int buf = 0;
    for (int p = warpG; p < GP; p += warpsTotal, buf ^= 1) {
        int pn = p + warpsTotal; if (pn >= GP) pn = GP - 1;
        prefetch(pn, buf ^ 1);
        const int mcur = mnext;
        if (lane < 20) mnext = __ldg(mask + (size_t)pn * 20 + lane);
        CPA_WAIT1();
        __syncwarp();

        const int g = 2 * p + hf;
        const size_t gDP  = (size_t)g * DP;
        const size_t gNDP = (size_t)g * (N * DP);

        const unsigned bal = __ballot_sync(FULL, (lane < 20) && (mcur != 0));
        unsigned vm = (bal >> (hf * 10)) & 0x3FFu;
        int cnt = __popc(vm);
        if (cnt == 0) { vm = 0x3FFu; cnt = N; }

        // ---- h-tasks + uq-tasks ----
#pragma unroll
        for (int r = 0; r < 3; r++) {
            if (r < 2 || lane < 16) {
                const int t_id = r * 32 + lane;
                const int row = t_id >> 2;
                const ulonglong2 pp = wb.pbuf[buf][row];
                float px, py, pz, pw; up2(pp.x, px, py); up2(pp.y, pz, pw);
                float ph = pb1c;
                ph = fmaf(px, pw1c0, ph);
                ph = fmaf(py, pw1c1, ph);
                ph = fmaf(pz, pw1c2, ph);
                ph = fmaf(pw, pw1c3, ph);
                wb.ph[t_id] = fmaxf(ph, 0.f);
            }
        }
        if (lane >= 16 && lane < 24) {
            const int u = lane - 16, grp = u >> 2;
            ull acc = 0;
#pragma unroll
            for (int jj = 0; jj < 8; jj++) {
                const ulonglong2 q4 = wb.qbuf[buf][grp * 8 + jj];
                const ulonglong2 f4 = sFq[cML][jj];
                acc = fma2(q4.x, f4.x, acc);
                acc = fma2(q4.y, f4.y, acc);
            }
            float lo, hi; up2(acc, lo, hi);
            wb.uq[u] = sCB[cML] - (lo + hi);
        }
        __syncwarp();

        // ---- y-tasks on RAW k ----
        {
            const ulonglong2* kb = wb.kbuf[buf];
#pragma unroll
            for (int r = 0; r < 3; r++) {
                if (r < 2 || lane < 16) {
                    const int t_id = r * 32 + lane;
                    const int row = t_id >> 2;
                    const int sw = row & 7;
                    ull acc = 0;
#pragma unroll
                    for (int jj = 0; jj < 8; jj++) {
                        const ulonglong2 kk = kb[row * 8 + (jj ^ sw)];
                        const ulonglong2 ff = sFk[cML][jj];
                        acc = fma2(kk.x, ff.x, acc);
                        acc = fma2(kk.y, ff.y, acc);
                    }
                    float lo, hi; up2(acc, lo, hi);
                    float s = lo + hi + wb.uq[(row >= 10 ? 4 : 0) + cML];
                    const float4 p4 = *(const float4*)&wb.ph[row * 4];
                    const float4 m4 = *(const float4*)&sM[cML][0];
                    s = fmaf(p4.x, m4.x, s);
                    s = fmaf(p4.y, m4.y, s);
                    s = fmaf(p4.z, m4.z, s);
                    s = fmaf(p4.w, m4.w, s);
                    wb.yv[t_id] = fmaxf(s, 0.f);
                }
            }
        }

        // ---- kp/vp projections: j-pair chains, NO dup2; n blocked 5+5 ----
        ull kp[N], vp[N];
#pragma unroll
        for (int half = 0; half < 2; half++) {
            ull a0[5], a1[5], a2c[5], a3[5];
#pragma unroll
            for (int nn = 0; nn < 5; nn++) { a0[nn]=0; a1[nn]=0; a2c[nn]=0; a3[nn]=0; }
#pragma unroll
            for (int j4 = 0; j4 < 8; j4++) {
                const ulonglong2 wkA = *(const ulonglong2*)&sWkJ[2*j4][d2];
                const ulonglong2 wkB = *(const ulonglong2*)&sWkJ[2*j4+1][d2];
                const ulonglong2 wvA = *(const ulonglong2*)&sWvJ[2*j4][d2];
                const ulonglong2 wvB = *(const ulonglong2*)&sWvJ[2*j4+1][d2];
#pragma unroll
                for (int nn = 0; nn < 5; nn++) {
                    const int row = hf * 10 + half * 5 + nn;
                    const ulonglong2 kk = wb.kbuf[buf][row * 8 + (j4 ^ (row & 7))];
                    a0[nn] = fma2(kk.x, wkA.x, a0[nn]);
                    a0[nn] = fma2(kk.y, wkB.x, a0[nn]);
                    a1[nn] = fma2(kk.x, wkA.y, a1[nn]);
                    a1[nn] = fma2(kk.y, wkB.y, a1[nn]);
                    a2c[nn] = fma2(kk.x, wvA.x, a2c[nn]);
                    a2c[nn] = fma2(kk.y, wvB.x, a2c[nn]);
                    a3[nn] = fma2(kk.x, wvA.y, a3[nn]);
                    a3[nn] = fma2(kk.y, wvB.y, a3[nn]);
                }
            }
#pragma unroll
            for (int nn = 0; nn < 5; nn++) {
                const int n = half * 5 + nn;
                float l0, h0, l1, h1;
                up2(a0[nn], l0, h0); up2(a1[nn], l1, h1);
                kp[n] = pk2(l0 + h0, l1 + h1);
                up2(a2c[nn], l0, h0); up2(a3[nn], l1, h1);
                vp[n] = pk2(l0 + h0, l1 + h1);
            }
        }
        __syncwarp();   // y-task writes visible; kbuf reads complete

        // ---- epilogue per n: stats, pe->vp, scores (h-pair chains) ----
        ull ksum = 0, kabs = 0, ksq = 0, sA[N];
#pragma unroll
        for (int n = 0; n < N; n++) {
            const int row = hf * 10 + n;
            const float mk = ((vm >> n) & 1u) ? 1.f : 0.f;
            const ull md = dup2(mk);
            const ull kpm = mul2(kp[n], md);
            ksum = add2(ksum, kpm);
            kabs = add2(kabs, kpm & ABS2);
            ksq  = fma2(kpm, kp[n], ksq);

            const ull ph01 = *(const ull*)&wb.ph[row * 4];
            const ull ph23 = *(const ull*)&wb.ph[row * 4 + 2];
            ull c0 = fma2(ph23, wpB.x, mul2(ph01, wpA.x));
            ull c1 = fma2(ph23, wpB.y, mul2(ph01, wpA.y));
            float l0, h0, l1, h1; up2(c0, l0, h0); up2(c1, l1, h1);
            vp[n] = add2(vp[n], add2(pk2(l0 + h0, l1 + h1), pb2p));

            const ull y01 = *(const ull*)&wb.yv[row * 4];
            const ull y23 = *(const ull*)&wb.yv[row * 4 + 2];
            ull s0 = fma2(y23, waB.x, mul2(y01, waA.x));
            ull s1 = fma2(y23, waB.y, mul2(y01, waA.y));
            up2(s0, l0, h0); up2(s1, l1, h1);
            sA[n] = add2(pk2(l0 + h0, l1 + h1), ab2p);
        }

        // ---- masked softmax over n ----
        float mxl = -3e38f, mxh = -3e38f;
#pragma unroll
        for (int n = 0; n < N; n++) {
            float lo, hi; up2(sA[n], lo, hi);
            if ((vm >> n) & 1u) { mxl = fmaxf(mxl, lo); mxh = fmaxf(mxh, hi); }
        }
        float esl = 0.f, esh = 0.f;
#pragma unroll
        for (int n = 0; n < N; n++) {
            float lo, hi; up2(sA[n], lo, hi);
            const bool v = (vm >> n) & 1u;
            const float el = v ? __expf(lo - mxl) : 0.f;
            const float eh = v ? __expf(hi - mxh) : 0.f;
            sA[n] = pk2(el, eh);
            esl += el; esh += eh;
        }
        const ull sinvp = pk2(__fdividef(1.f, esl), __fdividef(1.f, esh));

        // ---- attn out + weighted sum ----
        ull xv = 0;
#pragma unroll
        for (int n = 0; n < N; n++) {
            const ull a = mul2(sA[n], sinvp);
            out_attn[gNDP + n * DP + gl] = a;
            xv = fma2(vp[n], a, xv);
        }

        // ---- stats finale ----
        const float cinv = __fdividef(1.f, (float)cnt);
        const ull meanp = mul2(ksum, dup2(cinv));
        const ull mabsp = mul2(kabs, dup2(cinv));
        const ull cm2 = mul2(mul2(meanp, meanp), dup2((float)cnt));
        ull varp = add2(ksq, cm2 ^ SGN2);
        const float rdc = __fdividef(1.f, fmaxf((float)(cnt - 1), 1.f));
        varp = mul2(varp, dup2(rdc));
        float vl, vh, mal, mah; up2(varp, vl, vh); up2(mabsp, mal, mah);
        float stl = 0.f, sth = 0.f, nsl = 0.f, nsh = 0.f;
        if (cnt > 1) {
            stl = sqrtf(fmaxf(vl, 0.f)); sth = sqrtf(fmaxf(vh, 0.f));
            nsl = stl / (mal + 1e-6f);   nsh = sth / (mah + 1e-6f);
        }

        // ---- x = xv @ oW + ob (dup'd xv in dead kbuf[buf]) ----
        {
            ulonglong2* xd = wb.kbuf[buf];
            float xl, xh; up2(xv, xl, xh);
            ulonglong2 t; t.x = dup2(xl); t.y = dup2(xh);
            xd[hf * 16 + gl] = t;
        }
        __syncwarp();
        ull xo = obp;
#pragma unroll
        for (int jx = 0; jx < 8; jx++) {
            const ulonglong2 x01 = wb.kbuf[buf][hf * 16 + 2 * jx];
            const ulonglong2 x23 = wb.kbuf[buf][hf * 16 + 2 * jx + 1];
            const ulonglong2 w01 = sOWP[2 * jx][gl];
            const ulonglong2 w23 = sOWP[2 * jx + 1][gl];
            xo = fma2(x01.x, w01.x, xo);
            xo = fma2(x01.y, w01.y, xo);
            xo = fma2(x23.x, w23.x, xo);
            xo = fma2(x23.y, w23.y, xo);
        }
        out_x[gDP + gl]    = xo;
        out_std[gDP + gl]  = pk2(stl, sth);
        out_nstd[gDP + gl] = pk2(nsl, nsh);
        __syncwarp();   // protect reused regions before next iteration
    }
}

extern "C" void kernel_launch(void* const* d_in, const int* in_sizes, int n_in,
                              void* d_out, int out_size)
{
    const float* q    = (const float*)d_in[0];
    const float* k    = (const float*)d_in[1];
    const float* pos  = (const float*)d_in[2];
    const int*   mask = (const int*)  d_in[3];
    const float* Wq   = (const float*)d_in[4];
    const float* Wk   = (const float*)d_in[5];
    const float* Wv   = (const float*)d_in[6];
    const float* pW1  = (const float*)d_in[7];
    const float* pb1  = (const float*)d_in[8];
    const float* pW2  = (const float*)d_in[9];
    const float* pb2  = (const float*)d_in[10];
    const float* aW1  = (const float*)d_in[11];
    const float* ab1  = (const float*)d_in[12];
    const float* aW2  = (const float*)d_in[13];
    const float* ab2  = (const float*)d_in[14];
    const float* oW   = (const float*)d_in[15];
    const float* ob   = (const float*)d_in[16];

    const int G = in_sizes[0] / D;

    float* base     = (float*)d_out;
    ull*   out_x    = (ull*)base;
    ull*   out_attn = (ull*)(base + (size_t)G * D);
    ull*   out_std  = (ull*)(base + (size_t)G * D + (size_t)G * N * D);
    ull*   out_nstd = (ull*)(base + 2 * (size_t)G * D + (size_t)G * N * D);

    const int threads = 128;
    const int blocks  = 608;   // 4 blocks/SM persistent on 152 SMs
    attn2d_kernel<<<blocks, threads>>>(
        q, k, pos, mask, Wq, Wk, Wv,
        pW1, pb1, pW2, pb2, aW1, ab1, aW2, ab2, oW, ob,
        out_x, out_attn, out_std, out_nstd, G);
}

// round 12
// speedup vs baseline: 1.6079x; 1.6079x over previous
#include <cuda_runtime.h>
#include <math.h>

#define FULL 0xFFFFFFFFu
using ull = unsigned long long;

constexpr int D  = 32;
constexpr int N  = 10;
constexpr int H  = 4;
constexpr int DP = 16;   // dim-pairs; 16 lanes/group, 2 groups/warp

constexpr ull SGN2 = 0x8000000080000000ULL;
constexpr ull ABS2 = 0x7FFFFFFF7FFFFFFFULL;

__device__ __forceinline__ ull pk2(float lo, float hi) {
    ull r; asm("mov.b64 %0,{%1,%2};" : "=l"(r) : "f"(lo), "f"(hi)); return r;
}
__device__ __forceinline__ ull dup2(float v) {
    ull r; asm("mov.b64 %0,{%1,%1};" : "=l"(r) : "f"(v)); return r;
}
__device__ __forceinline__ void up2(ull p, float& lo, float& hi) {
    asm("mov.b64 {%0,%1},%2;" : "=f"(lo), "=f"(hi) : "l"(p));
}
__device__ __forceinline__ ull fma2(ull a, ull b, ull c) {
    ull r; asm("fma.rn.f32x2 %0,%1,%2,%3;" : "=l"(r) : "l"(a), "l"(b), "l"(c)); return r;
}
__device__ __forceinline__ ull add2(ull a, ull b) {
    ull r; asm("add.rn.f32x2 %0,%1,%2;" : "=l"(r) : "l"(a), "l"(b)); return r;
}
__device__ __forceinline__ ull mul2(ull a, ull b) {
    ull r; asm("mul.rn.f32x2 %0,%1,%2;" : "=l"(r) : "l"(a), "l"(b)); return r;
}
__device__ __forceinline__ void cpa16(unsigned s, const void* g) {
    asm volatile("cp.async.cg.shared.global [%0],[%1],16;" :: "r"(s), "l"(g));
}
#define CPA_COMMIT() asm volatile("cp.async.commit_group;" ::: "memory")
#define CPA_WAIT1()  asm volatile("cp.async.wait_group 1;" ::: "memory")

struct WB {
    ulonglong2 kbuf[2][160];  // k staging, PRE-SWIZZLED; cur buf reused for xv-dup
    ulonglong2 pbuf[2][20];   // pos
    ulonglong2 qbuf[2][16];   // q
    float ph[80];             // relu'd pos-MLP hidden units (row*4+c)
    float yv[80];             // relu'd score-MLP hidden units (row*4+c)
    float uq[8];              // per-group c-constants: ab1+cb-q.Fq
};

__global__ void __launch_bounds__(128, 4) attn2d_kernel(
    const float* __restrict__ q,   const float* __restrict__ k,
    const float* __restrict__ pos, const int*   __restrict__ mask,
    const float* __restrict__ Wq,  const float* __restrict__ Wk,
    const float* __restrict__ Wv,
    const float* __restrict__ pW1, const float* __restrict__ pb1,
    const float* __restrict__ pW2, const float* __restrict__ pb2,
    const float* __restrict__ aW1, const float* __restrict__ ab1,
    const float* __restrict__ aW2, const float* __restrict__ ab2,
    const float* __restrict__ oW,  const float* __restrict__ ob,
    ull* __restrict__ out_x,  ull* __restrict__ out_attn,
    ull* __restrict__ out_std, ull* __restrict__ out_nstd,
    int G)
{
    __shared__ __align__(16) ulonglong2 sWkP[16][16];
    __shared__ __align__(16) ulonglong2 sWvP[16][16];
    __shared__ __align__(16) ulonglong2 sOWP[16][16];
    __shared__ __align__(16) ull sP2J[2][32];        // (pW2[2h][d], pW2[2h+1][d])
    __shared__ __align__(16) ull sA2J[2][32];        // (aW2[2h][d], aW2[2h+1][d])
    __shared__ __align__(16) ulonglong2 sFk[4][9];   // Wk@aW1 col c packed, stride-9 pad
    __shared__ __align__(16) ulonglong2 sFq[4][9];   // Wq@aW1 col c packed
    __shared__ __align__(16) float sM[4][4];         // sM[c][h] = (pW2@aW1)[h][c]
    __shared__ float sCB[4];                         // ab1[c] + pb2.aW1[:,c]
    __shared__ __align__(16) WB wbuf[4];

    const int tid = threadIdx.x;
    // ---- phase 0: fused-weight raw compute (into temp) + big-weight staging ----
    float* tmpF = (float*)wbuf[0].kbuf;   // 256 floats temp: Fk then Fq, idx j*4+c
    {
        const int j = tid >> 2, c = tid & 3;
        float fk = 0.f, fq = 0.f;
        for (int d = 0; d < D; d++) {
            const float a = aW1[d * H + c];
            fk = fmaf(Wk[j * D + d], a, fk);
            fq = fmaf(Wq[j * D + d], a, fq);
        }
        tmpF[tid] = fk; tmpF[128 + tid] = fq;
    }
    for (int i = tid; i < 256; i += 128) {   // row-pair interleaved weights
        const int j2 = i >> 4, gl2 = (i & 15) * 2;
        ulonglong2 t;
        t.x = pk2(Wk[(2*j2)*D + gl2],   Wk[(2*j2)*D + gl2+1]);
        t.y = pk2(Wk[(2*j2+1)*D + gl2], Wk[(2*j2+1)*D + gl2+1]);
        sWkP[j2][i & 15] = t;
        t.x = pk2(Wv[(2*j2)*D + gl2],   Wv[(2*j2)*D + gl2+1]);
        t.y = pk2(Wv[(2*j2+1)*D + gl2], Wv[(2*j2+1)*D + gl2+1]);
        sWvP[j2][i & 15] = t;
        t.x = pk2(oW[(2*j2)*D + gl2],   oW[(2*j2)*D + gl2+1]);
        t.y = pk2(oW[(2*j2+1)*D + gl2], oW[(2*j2+1)*D + gl2+1]);
        sOWP[j2][i & 15] = t;
    }
    if (tid < 64) {   // h-pair epilogue weight packs
        const int h2 = tid >> 5, d = tid & 31;
        sP2J[h2][d] = pk2(pW2[(2*h2)*D + d], pW2[(2*h2+1)*D + d]);
        sA2J[h2][d] = pk2(aW2[(2*h2)*D + d], aW2[(2*h2+1)*D + d]);
    }
    if (tid < 16) {
        const int h = tid >> 2, c = tid & 3;
        float m = 0.f;
        for (int d = 0; d < D; d++) m = fmaf(pW2[h * D + d], aW1[d * H + c], m);
        sM[c][h] = m;
    }
    if (tid < 4) {
        float cb = ab1[tid];
        for (int d = 0; d < D; d++) cb = fmaf(pb2[d], aW1[d * H + tid], cb);
        sCB[tid] = cb;
    }
    __syncthreads();
    if (tid < 32) {   // repack fused weights by column, dim-pair packed
        const int c = tid >> 3, jj = tid & 7;
        ulonglong2 t;
        t.x = pk2(tmpF[(4*jj+0)*4 + c], tmpF[(4*jj+1)*4 + c]);
        t.y = pk2(tmpF[(4*jj+2)*4 + c], tmpF[(4*jj+3)*4 + c]);
        sFk[c][jj] = t;
        t.x = pk2(tmpF[128 + (4*jj+0)*4 + c], tmpF[128 + (4*jj+1)*4 + c]);
        t.y = pk2(tmpF[128 + (4*jj+2)*4 + c], tmpF[128 + (4*jj+3)*4 + c]);
        sFq[c][jj] = t;
    }
    __syncthreads();   // tmpF dead; wbuf usable

    const int lane = tid & 31, gl = lane & 15, hf = lane >> 4, w = tid >> 5;
    const int d2 = 2 * gl;
    const int cML = lane & 3;
    const float pb1c = pb1[cML];
    const float pw1c0 = pW1[0*H + cML], pw1c1 = pW1[1*H + cML];
    const float pw1c2 = pW1[2*H + cML], pw1c3 = pW1[3*H + cML];

    // hoisted h-pair epilogue weights (register-neutral swap for a2p/p2p arrays)
    const ulonglong2 wpA = *(const ulonglong2*)&sP2J[0][d2];
    const ulonglong2 wpB = *(const ulonglong2*)&sP2J[1][d2];
    const ulonglong2 waA = *(const ulonglong2*)&sA2J[0][d2];
    const ulonglong2 waB = *(const ulonglong2*)&sA2J[1][d2];
    const ull pb2p = pk2(pb2[d2], pb2[d2 + 1]);
    const ull ab2p = pk2(ab2[d2], ab2[d2 + 1]);
    const ull obp  = pk2(ob[d2],  ob[d2 + 1]);

    WB& wb = wbuf[w];
    const int warpsTotal = (gridDim.x * blockDim.x) >> 5;
    const int warpG = (blockIdx.x * blockDim.x + tid) >> 5;
    const int GP = G >> 1;

    auto prefetch = [&](int pp, int nb) {
        const ulonglong2* kf = (const ulonglong2*)k + (size_t)pp * 160;
        ulonglong2* kb = wb.kbuf[nb];
#pragma unroll
        for (int i = 0; i < 5; i++) {
            const int flat = i * 32 + lane;
            const int row = flat >> 3, j4 = flat & 7;
            cpa16((unsigned)__cvta_generic_to_shared(kb + row * 8 + (j4 ^ (row & 7))),
                  kf + flat);
        }
        if (lane < 16)
            cpa16((unsigned)__cvta_generic_to_shared(&wb.qbuf[nb][lane]),
                  (const ulonglong2*)q + (size_t)pp * 16 + lane);
        if (lane < 20)
            cpa16((unsigned)__cvta_generic_to_shared(&wb.pbuf[nb][lane]),
                  (const ulonglong2*)pos + (size_t)pp * 20 + lane);
        CPA_COMMIT();
    };

    int mnext = 0;
    if (warpG < GP) {
        prefetch(warpG, 0);
        if (lane < 20) mnext = __ldg(mask + (size_t)warpG * 20 + lane);
    }

    int buf = 0;
    for (int p = warpG; p < GP; p += warpsTotal, buf ^= 1) {
        int pn = p + warpsTotal; if (pn >= GP) pn = GP - 1;
        prefetch(pn, buf ^ 1);
        const int mcur = mnext;
        if (lane < 20) mnext = __ldg(mask + (size_t)pn * 20 + lane);
        CPA_WAIT1();
        __syncwarp();

        const int g = 2 * p + hf;
        const size_t gDP  = (size_t)g * DP;
        const size_t gNDP = (size_t)g * (N * DP);

        const unsigned bal = __ballot_sync(FULL, (lane < 20) && (mcur != 0));
        unsigned vm = (bal >> (hf * 10)) & 0x3FFu;
        int cnt = __popc(vm);
        if (cnt == 0) { vm = 0x3FFu; cnt = N; }

        // ---- h-tasks (80 hidden units, dedup'd) + uq-tasks (8 per-group consts) ----
#pragma unroll
        for (int r = 0; r < 3; r++) {
            if (r < 2 || lane < 16) {
                const int t_id = r * 32 + lane;
                const int row = t_id >> 2;
                const ulonglong2 pp = wb.pbuf[buf][row];
                float px, py, pz, pw; up2(pp.x, px, py); up2(pp.y, pz, pw);
                float ph = pb1c;
                ph = fmaf(px, pw1c0, ph);
                ph = fmaf(py, pw1c1, ph);
                ph = fmaf(pz, pw1c2, ph);
                ph = fmaf(pw, pw1c3, ph);
                wb.ph[t_id] = fmaxf(ph, 0.f);
            }
        }
        if (lane >= 16 && lane < 24) {   // uq: grp = (lane-16)>>2, c = lane&3
            const int u = lane - 16, grp = u >> 2;
            ull acc = 0;
#pragma unroll
            for (int jj = 0; jj < 8; jj++) {
                const ulonglong2 q4 = wb.qbuf[buf][grp * 8 + jj];
                const ulonglong2 f4 = sFq[cML][jj];
                acc = fma2(q4.x, f4.x, acc);
                acc = fma2(q4.y, f4.y, acc);
            }
            float lo, hi; up2(acc, lo, hi);
            wb.uq[u] = sCB[cML] - (lo + hi);
        }
        __syncwarp();

        // ---- y-tasks: y = relu(k.Fk[:,c] + uq + ph.M[:,c]) on RAW k ----
        {
            const ulonglong2* kb = wb.kbuf[buf];
#pragma unroll
            for (int r = 0; r < 3; r++) {
                if (r < 2 || lane < 16) {
                    const int t_id = r * 32 + lane;
                    const int row = t_id >> 2;
                    const int sw = row & 7;
                    ull acc = 0;
#pragma unroll
                    for (int jj = 0; jj < 8; jj++) {
                        const ulonglong2 kk = kb[row * 8 + (jj ^ sw)];
                        const ulonglong2 ff = sFk[cML][jj];
                        acc = fma2(kk.x, ff.x, acc);
                        acc = fma2(kk.y, ff.y, acc);
                    }
                    float lo, hi; up2(acc, lo, hi);
                    float s = lo + hi + wb.uq[(row >= 10 ? 4 : 0) + cML];
                    const float4 p4 = *(const float4*)&wb.ph[row * 4];
                    const float4 m4 = *(const float4*)&sM[cML][0];
                    s = fmaf(p4.x, m4.x, s);
                    s = fmaf(p4.y, m4.y, s);
                    s = fmaf(p4.z, m4.z, s);
                    s = fmaf(p4.w, m4.w, s);
                    wb.yv[t_id] = fmaxf(s, 0.f);
                }
            }
        }

        // ---- kp/vp projections (R8 form: dim-pair weights, dup2 broadcast) ----
        ull kp[N], vp[N];
#pragma unroll
        for (int n = 0; n < N; n++) { kp[n] = 0; vp[n] = 0; }
#pragma unroll
        for (int j4 = 0; j4 < 8; j4++) {
            const ulonglong2 wk01 = sWkP[2 * j4][gl];
            const ulonglong2 wk23 = sWkP[2 * j4 + 1][gl];
            const ulonglong2 wv01 = sWvP[2 * j4][gl];
            const ulonglong2 wv23 = sWvP[2 * j4 + 1][gl];
#pragma unroll
            for (int n = 0; n < N; n++) {
                const int row = hf * 10 + n;
                const ulonglong2 kk = wb.kbuf[buf][row * 8 + (j4 ^ (row & 7))];
                float k0, k1, k2, k3; up2(kk.x, k0, k1); up2(kk.y, k2, k3);
                const ull d0 = dup2(k0), d1 = dup2(k1), d2d = dup2(k2), d3 = dup2(k3);
                kp[n] = fma2(d0, wk01.x, kp[n]);
                kp[n] = fma2(d1, wk01.y, kp[n]);
                kp[n] = fma2(d2d, wk23.x, kp[n]);
                kp[n] = fma2(d3, wk23.y, kp[n]);
                vp[n] = fma2(d0, wv01.x, vp[n]);
                vp[n] = fma2(d1, wv01.y, vp[n]);
                vp[n] = fma2(d2d, wv23.x, vp[n]);
                vp[n] = fma2(d3, wv23.y, vp[n]);
            }
        }
        __syncwarp();   // y-task writes visible; kbuf reads complete

        // ---- epilogue per n: stats, pe->vp, scores (h-pair chains, no dup2) ----
        ull ksum = 0, kabs = 0, ksq = 0, sA[N];
#pragma unroll
        for (int n = 0; n < N; n++) {
            const int row = hf * 10 + n;
            const float mk = ((vm >> n) & 1u) ? 1.f : 0.f;
            const ull md = dup2(mk);
            const ull kpm = mul2(kp[n], md);
            ksum = add2(ksum, kpm);
            kabs = add2(kabs, kpm & ABS2);
            ksq  = fma2(kpm, kp[n], ksq);

            const ull ph01 = *(const ull*)&wb.ph[row * 4];
            const ull ph23 = *(const ull*)&wb.ph[row * 4 + 2];
            ull c0 = fma2(ph23, wpB.x, mul2(ph01, wpA.x));
            ull c1 = fma2(ph23, wpB.y, mul2(ph01, wpA.y));
            float l0, h0, l1, h1; up2(c0, l0, h0); up2(c1, l1, h1);
            vp[n] = add2(vp[n], add2(pk2(l0 + h0, l1 + h1), pb2p));

            const ull y01 = *(const ull*)&wb.yv[row * 4];
            const ull y23 = *(const ull*)&wb.yv[row * 4 + 2];
            ull s0 = fma2(y23, waB.x, mul2(y01, waA.x));
            ull s1 = fma2(y23, waB.y, mul2(y01, waA.y));
            up2(s0, l0, h0); up2(s1, l1, h1);
            sA[n] = add2(pk2(l0 + h0, l1 + h1), ab2p);
        }

        // ---- masked softmax over n ----
        float mxl = -3e38f, mxh = -3e38f;
#pragma unroll
        for (int n = 0; n < N; n++) {
            float lo, hi; up2(sA[n], lo, hi);
            if ((vm >> n) & 1u) { mxl = fmaxf(mxl, lo); mxh = fmaxf(mxh, hi); }
        }
        float esl = 0.f, esh = 0.f;
#pragma unroll
        for (int n = 0; n < N; n++) {
            float lo, hi; up2(sA[n], lo, hi);
            const bool v = (vm >> n) & 1u;
            const float el = v ? __expf(lo - mxl) : 0.f;
            const float eh = v ? __expf(hi - mxh) : 0.f;
            sA[n] = pk2(el, eh);
            esl += el; esh += eh;
        }
        const ull sinvp = pk2(__fdividef(1.f, esl), __fdividef(1.f, esh));

        // ---- attn out + weighted sum ----
        ull xv = 0;
#pragma unroll
        for (int n = 0; n < N; n++) {
            const ull a = mul2(sA[n], sinvp);
            out_attn[gNDP + n * DP + gl] = a;
            xv = fma2(vp[n], a, xv);
        }

        // ---- stats finale ----
        const float cinv = __fdividef(1.f, (float)cnt);
        const ull meanp = mul2(ksum, dup2(cinv));
        const ull mabsp = mul2(kabs, dup2(cinv));
        const ull cm2 = mul2(mul2(meanp, meanp), dup2((float)cnt));
        ull varp = add2(ksq, cm2 ^ SGN2);
        const float rdc = __fdividef(1.f, fmaxf((float)(cnt - 1), 1.f));
        varp = mul2(varp, dup2(rdc));
        float vl, vh, mal, mah; up2(varp, vl, vh); up2(mabsp, mal, mah);
        float stl = 0.f, sth = 0.f, nsl = 0.f, nsh = 0.f;
        if (cnt > 1) {
            stl = sqrtf(fmaxf(vl, 0.f)); sth = sqrtf(fmaxf(vh, 0.f));
            nsl = stl / (mal + 1e-6f);   nsh = sth / (mah + 1e-6f);
        }

        // ---- x = xv @ oW + ob (dup'd xv in dead kbuf[buf]) ----
        {
            ulonglong2* xd = wb.kbuf[buf];
            float xl, xh; up2(xv, xl, xh);
            ulonglong2 t; t.x = dup2(xl); t.y = dup2(xh);
            xd[hf * 16 + gl] = t;
        }
        __syncwarp();
        ull xo = obp;
#pragma unroll
        for (int jx = 0; jx < 8; jx++) {
            const ulonglong2 x01 = wb.kbuf[buf][hf * 16 + 2 * jx];
            const ulonglong2 x23 = wb.kbuf[buf][hf * 16 + 2 * jx + 1];
            const ulonglong2 w01 = sOWP[2 * jx][gl];
            const ulonglong2 w23 = sOWP[2 * jx + 1][gl];
            xo = fma2(x01.x, w01.x, xo);
            xo = fma2(x01.y, w01.y, xo);
            xo = fma2(x23.x, w23.x, xo);
            xo = fma2(x23.y, w23.y, xo);
        }
        out_x[gDP + gl]    = xo;
        out_std[gDP + gl]  = pk2(stl, sth);
        out_nstd[gDP + gl] = pk2(nsl, nsh);
        __syncwarp();   // protect reused regions before next iteration
    }
}

extern "C" void kernel_launch(void* const* d_in, const int* in_sizes, int n_in,
                              void* d_out, int out_size)
{
    const float* q    = (const float*)d_in[0];
    const float* k    = (const float*)d_in[1];
    const float* pos  = (const float*)d_in[2];
    const int*   mask = (const int*)  d_in[3];
    const float* Wq   = (const float*)d_in[4];
    const float* Wk   = (const float*)d_in[5];
    const float* Wv   = (const float*)d_in[6];
    const float* pW1  = (const float*)d_in[7];
    const float* pb1  = (const float*)d_in[8];
    const float* pW2  = (const float*)d_in[9];
    const float* pb2  = (const float*)d_in[10];
    const float* aW1  = (const float*)d_in[11];
    const float* ab1  = (const float*)d_in[12];
    const float* aW2  = (const float*)d_in[13];
    const float* ab2  = (const float*)d_in[14];
    const float* oW   = (const float*)d_in[15];
    const float* ob   = (const float*)d_in[16];

    const int G = in_sizes[0] / D;

    float* base     = (float*)d_out;
    ull*   out_x    = (ull*)base;
    ull*   out_attn = (ull*)(base + (size_t)G * D);
    ull*   out_std  = (ull*)(base + (size_t)G * D + (size_t)G * N * D);
    ull*   out_nstd = (ull*)(base + 2 * (size_t)G * D + (size_t)G * N * D);

    const int threads = 128;
    const int blocks  = 608;   // 4 blocks/SM persistent on 152 SMs
    attn2d_kernel<<<blocks, threads>>>(
        q, k, pos, mask, Wq, Wk, Wv,
        pW1, pb1, pW2, pb2, aW1, ab1, aW2, ab2, oW, ob,
        out_x, out_attn, out_std, out_nstd, G);
}